// round 1
// baseline (speedup 1.0000x reference)
#include <cuda_runtime.h>

#define D 128
#define DV 32            // float4 per row
#define BM 64            // gemm rows per block
#define MAXN 100352
#define MAXE 1700000

// ---------------- scratch (device globals: no allocation allowed) -------------
__device__ float g_h[MAXN * D];
__device__ float g_x[MAXN * D];
__device__ float g_y[MAXN * D];
__device__ float g_dinv[MAXN];
__device__ int   g_deg[MAXN];
__device__ int   g_rowstart[MAXN + 1];
__device__ int   g_cursor[MAXN];
__device__ int   g_csr_src[MAXE];
__device__ float g_csr_norm[MAXE];

// ---------------- degree / normalization ------------------------------------
__global__ void zero_deg_kernel(int n) {
    int i = blockIdx.x * blockDim.x + threadIdx.x;
    if (i < n) g_deg[i] = 0;
}

__global__ void count_deg_kernel(const int* __restrict__ dst, int E) {
    int e = blockIdx.x * blockDim.x + threadIdx.x;
    if (e < E) atomicAdd(&g_deg[dst[e]], 1);
}

__global__ void dinv_kernel(int n) {
    int i = blockIdx.x * blockDim.x + threadIdx.x;
    if (i < n) {
        // deg includes +1 self loop; always >= 1 so max(deg,1) is moot
        g_dinv[i] = rsqrtf((float)(g_deg[i] + 1));
    }
}

// single-block exclusive scan of g_deg -> g_rowstart / g_cursor
__global__ void scan_kernel(int n) {
    __shared__ int s[1024];
    int t = threadIdx.x;
    int C = (n + 1023) >> 10;           // elems per thread
    int lo = t * C;
    int hi = lo + C; if (hi > n) hi = n;
    int sum = 0;
    for (int i = lo; i < hi; ++i) sum += g_deg[i];
    s[t] = sum;
    __syncthreads();
    // Hillis-Steele inclusive scan over 1024 partials
    for (int o = 1; o < 1024; o <<= 1) {
        int v = (t >= o) ? s[t - o] : 0;
        __syncthreads();
        s[t] += v;
        __syncthreads();
    }
    int run = s[t] - sum;               // exclusive offset for this chunk
    for (int i = lo; i < hi; ++i) {
        g_rowstart[i] = run;
        g_cursor[i]   = run;
        run += g_deg[i];
    }
    if (t == 1023) g_rowstart[n] = s[1023];
}

__global__ void fill_kernel(const int* __restrict__ src, const int* __restrict__ dst, int E) {
    int e = blockIdx.x * blockDim.x + threadIdx.x;
    if (e >= E) return;
    int u = src[e], v = dst[e];
    int slot = atomicAdd(&g_cursor[v], 1);
    g_csr_src[slot]  = u;
    g_csr_norm[slot] = g_dinv[u] * g_dinv[v];
}

// ---------------- GEMM: out = X @ W (+epilogues) -----------------------------
// epi: 0 = none; 1 = relu(acc + bias); 2 = acc + bias + add[row]
__global__ void gemm_kernel(const float* __restrict__ X, const float* __restrict__ W,
                            const float* __restrict__ bias, const float* __restrict__ add,
                            float* __restrict__ out, int M, int epi) {
    extern __shared__ float sm[];
    float* Ws = sm;              // 128*128
    float* Xs = sm + D * D;      // BM*128
    int row0 = blockIdx.x * BM;

    // load full W (64KB)
    const float4* W4 = (const float4*)W;
    float4* Ws4w = (float4*)Ws;
    for (int i = threadIdx.x; i < D * D / 4; i += 256) Ws4w[i] = W4[i];

    // load X tile (guard rows)
    const float4* X4 = (const float4*)X;
    float4* Xs4 = (float4*)Xs;
    for (int i = threadIdx.x; i < BM * D / 4; i += 256) {
        int r = i >> 5;           // 32 float4 per row
        int c = i & 31;
        int gr = row0 + r;
        float4 v = make_float4(0.f, 0.f, 0.f, 0.f);
        if (gr < M) v = X4[gr * DV + c];
        Xs4[i] = v;
    }
    __syncthreads();

    int tx = threadIdx.x & 31;    // cols 4*tx .. 4*tx+3
    int ty = threadIdx.x >> 5;    // rows ty*8 .. ty*8+7
    float acc[8][4];
    #pragma unroll
    for (int r = 0; r < 8; ++r)
        #pragma unroll
        for (int c = 0; c < 4; ++c) acc[r][c] = 0.f;

    const float4* Ws4 = (const float4*)Ws;
    const float* Xrow = Xs + (ty * 8) * D;

    #pragma unroll 8
    for (int k = 0; k < D; ++k) {
        float4 w = Ws4[k * DV + tx];
        #pragma unroll
        for (int r = 0; r < 8; ++r) {
            float xv = Xrow[r * D + k];
            acc[r][0] += xv * w.x;
            acc[r][1] += xv * w.y;
            acc[r][2] += xv * w.z;
            acc[r][3] += xv * w.w;
        }
    }

    float4 bv = make_float4(0.f, 0.f, 0.f, 0.f);
    if (epi != 0) bv = ((const float4*)bias)[tx];
    float4* out4 = (float4*)out;
    const float4* add4 = (const float4*)add;

    #pragma unroll
    for (int r = 0; r < 8; ++r) {
        int gr = row0 + ty * 8 + r;
        if (gr >= M) continue;
        float4 o;
        o.x = acc[r][0] + bv.x;
        o.y = acc[r][1] + bv.y;
        o.z = acc[r][2] + bv.z;
        o.w = acc[r][3] + bv.w;
        if (epi == 1) {
            o.x = fmaxf(o.x, 0.f); o.y = fmaxf(o.y, 0.f);
            o.z = fmaxf(o.z, 0.f); o.w = fmaxf(o.w, 0.f);
        } else if (epi == 2) {
            float4 a = add4[gr * DV + tx];
            o.x += a.x; o.y += a.y; o.z += a.z; o.w += a.w;
        }
        out4[gr * DV + tx] = o;
    }
}

// ---------------- fused aggregation + bias + LayerNorm (+ReLU) ---------------
// warp per node: out[v] = LN( dinv[v]^2*h[v] + sum_in norm*h[u] + bias )
__global__ void agg_ln_kernel(const float* __restrict__ h, const float* __restrict__ bias,
                              const float* __restrict__ gamma, const float* __restrict__ beta,
                              float* __restrict__ out, int N, int doRelu) {
    int gw   = (blockIdx.x * blockDim.x + threadIdx.x) >> 5;
    int lane = threadIdx.x & 31;
    if (gw >= N) return;
    int v = gw;

    const float4* h4 = (const float4*)h;
    float dv = g_dinv[v];
    float ds = dv * dv;
    float4 acc = h4[v * DV + lane];
    acc.x *= ds; acc.y *= ds; acc.z *= ds; acc.w *= ds;

    int s = g_rowstart[v];
    int e = g_rowstart[v + 1];
    for (int j = s; j < e; ++j) {
        int u   = g_csr_src[j];
        float n = g_csr_norm[j];
        float4 hv = h4[u * DV + lane];
        acc.x += hv.x * n; acc.y += hv.y * n;
        acc.z += hv.z * n; acc.w += hv.w * n;
    }

    float4 bv = ((const float4*)bias)[lane];
    acc.x += bv.x; acc.y += bv.y; acc.z += bv.z; acc.w += bv.w;

    // mean over 128
    float sum = acc.x + acc.y + acc.z + acc.w;
    #pragma unroll
    for (int o = 16; o > 0; o >>= 1) sum += __shfl_xor_sync(0xffffffffu, sum, o);
    float mu = sum * (1.0f / 128.0f);

    float cx = acc.x - mu, cy = acc.y - mu, cz = acc.z - mu, cw = acc.w - mu;
    float sq = cx * cx + cy * cy + cz * cz + cw * cw;
    #pragma unroll
    for (int o = 16; o > 0; o >>= 1) sq += __shfl_xor_sync(0xffffffffu, sq, o);
    float rs = rsqrtf(sq * (1.0f / 128.0f) + 1e-5f);

    float4 gv  = ((const float4*)gamma)[lane];
    float4 bev = ((const float4*)beta)[lane];
    float4 o;
    o.x = cx * rs * gv.x + bev.x;
    o.y = cy * rs * gv.y + bev.y;
    o.z = cz * rs * gv.z + bev.z;
    o.w = cw * rs * gv.w + bev.w;
    if (doRelu) {
        o.x = fmaxf(o.x, 0.f); o.y = fmaxf(o.y, 0.f);
        o.z = fmaxf(o.z, 0.f); o.w = fmaxf(o.w, 0.f);
    }
    ((float4*)out)[v * DV + lane] = o;
}

// ---------------- driver -----------------------------------------------------
extern "C" void kernel_launch(void* const* d_in, const int* in_sizes, int n_in,
                              void* d_out, int out_size) {
    const int*   edge_index = (const int*)d_in[0];
    const float* ent = (const float*)d_in[1];
    const float* W1  = (const float*)d_in[2];
    const float* b1  = (const float*)d_in[3];
    const float* g1  = (const float*)d_in[4];
    const float* be1 = (const float*)d_in[5];
    const float* W2  = (const float*)d_in[6];
    const float* b2  = (const float*)d_in[7];
    const float* g2  = (const float*)d_in[8];
    const float* be2 = (const float*)d_in[9];
    const float* W3  = (const float*)d_in[10];
    const float* b3  = (const float*)d_in[11];
    const float* g3  = (const float*)d_in[12];
    const float* be3 = (const float*)d_in[13];
    const float* Wt1 = (const float*)d_in[14];
    const float* bt1 = (const float*)d_in[15];
    const float* Wt2 = (const float*)d_in[16];
    const float* bt2 = (const float*)d_in[17];

    int E = in_sizes[0] / 2;
    int N = in_sizes[1] / D;
    const int* src = edge_index;
    const int* dst = edge_index + E;

    float *ph, *px, *py;
    cudaGetSymbolAddress((void**)&ph, g_h);
    cudaGetSymbolAddress((void**)&px, g_x);
    cudaGetSymbolAddress((void**)&py, g_y);

    const int SMEM = (D * D + BM * D) * sizeof(float);   // 96 KB
    cudaFuncSetAttribute(gemm_kernel, cudaFuncAttributeMaxDynamicSharedMemorySize, SMEM);

    int nb  = (N + 255) / 256;
    int eb  = (E + 255) / 256;
    int gg  = (N + BM - 1) / BM;
    int ab  = (N * 32 + 255) / 256;

    // graph preprocessing (CSR by dst, symmetric normalization)
    zero_deg_kernel<<<nb, 256>>>(N);
    count_deg_kernel<<<eb, 256>>>(dst, E);
    dinv_kernel<<<nb, 256>>>(N);
    scan_kernel<<<1, 1024>>>(N);
    fill_kernel<<<eb, 256>>>(src, dst, E);

    // layer 1
    gemm_kernel<<<gg, 256, SMEM>>>(ent, W1, nullptr, nullptr, ph, N, 0);
    agg_ln_kernel<<<ab, 256>>>(ph, b1, g1, be1, px, N, 1);
    // layer 2
    gemm_kernel<<<gg, 256, SMEM>>>(px, W2, nullptr, nullptr, ph, N, 0);
    agg_ln_kernel<<<ab, 256>>>(ph, b2, g2, be2, py, N, 1);
    // layer 3 (LN, no relu)
    gemm_kernel<<<gg, 256, SMEM>>>(py, W3, nullptr, nullptr, ph, N, 0);
    agg_ln_kernel<<<ab, 256>>>(ph, b3, g3, be3, px, N, 0);
    // transform MLP + residual with x0
    gemm_kernel<<<gg, 256, SMEM>>>(px, Wt1, bt1, nullptr, py, N, 1);
    gemm_kernel<<<gg, 256, SMEM>>>(py, Wt2, bt2, ent, (float*)d_out, N, 2);
}